// round 16
// baseline (speedup 1.0000x reference)
#include <cuda_runtime.h>
#include <cstdint>

// ---------------- problem constants ----------------
#define B_TOK  512
#define H_DIM  1024
#define I_DIM  1024
#define TWO_I  2048
#define N_EXP  32
#define TOPK   4
#define NPAIR  (B_TOK * TOPK)   // 2048

#define EPS_RMS   1e-5f
#define ALPHA_SG  1.702f
#define LIMIT_SG  7.0f

// ---------------- scratch (device globals; no allocations allowed) ----------
__device__ float d_t[B_TOK * H_DIM];        // normalized activations (2 MB)
__device__ float d_a[NPAIR * I_DIM];        // swiglu outputs per pair (8 MB)
__device__ float d_o[NPAIR * H_DIM];        // scaled expert outputs (8 MB)
__device__ int   d_gidx[B_TOK * TOPK];
__device__ float d_gw[B_TOK * TOPK];
__device__ int   d_cnt[N_EXP];
__device__ int   d_offs[N_EXP];
__device__ int   d_ptok[NPAIR];
__device__ float d_pw[NPAIR];
__device__ int   d_pslot[B_TOK * TOPK];

// ---------------- PTX helpers ----------------
__device__ __forceinline__ void mma_tf32(float* c, const uint32_t* a, const uint32_t* b) {
    asm volatile(
        "mma.sync.aligned.m16n8k8.row.col.f32.tf32.tf32.f32 "
        "{%0,%1,%2,%3}, {%4,%5,%6,%7}, {%8,%9}, {%0,%1,%2,%3};\n"
        : "+f"(c[0]), "+f"(c[1]), "+f"(c[2]), "+f"(c[3])
        : "r"(a[0]), "r"(a[1]), "r"(a[2]), "r"(a[3]), "r"(b[0]), "r"(b[1]));
}

__device__ __forceinline__ void ldm_x4(uint32_t& r0, uint32_t& r1, uint32_t& r2,
                                       uint32_t& r3, uint32_t addr) {
    asm volatile("ldmatrix.sync.aligned.m8n8.x4.shared.b16 {%0,%1,%2,%3}, [%4];"
                 : "=r"(r0), "=r"(r1), "=r"(r2), "=r"(r3) : "r"(addr));
}

__device__ __forceinline__ void cp_async16(float* dst, const float* src, int bytes = 16) {
    uint32_t s = (uint32_t)__cvta_generic_to_shared(dst);
    asm volatile("cp.async.cg.shared.global [%0], [%1], 16, %2;\n"
                 :: "r"(s), "l"(src), "r"(bytes) : "memory");
}
__device__ __forceinline__ void cp_commit() {
    asm volatile("cp.async.commit_group;\n" ::: "memory");
}

// ====================================================================
// K1: RMSNorm + gate logits + top-4 + softmax.  One block per token.
// ====================================================================
__global__ __launch_bounds__(256)
void route_kernel(const float* __restrict__ x,
                  const float* __restrict__ nsc,
                  const float* __restrict__ gw,
                  const float* __restrict__ gb)
{
    const int b   = blockIdx.x;
    const int tid = threadIdx.x;     // 256

    __shared__ float ts[H_DIM];
    __shared__ float red[8];
    __shared__ float gsm[N_EXP];

    float4 xv = reinterpret_cast<const float4*>(x)[b * 256 + tid];
    float ss = xv.x * xv.x + xv.y * xv.y + xv.z * xv.z + xv.w * xv.w;
    #pragma unroll
    for (int o = 16; o; o >>= 1) ss += __shfl_xor_sync(0xFFFFFFFFu, ss, o);
    if ((tid & 31) == 0) red[tid >> 5] = ss;
    __syncthreads();
    if (tid < 8) {
        float v = red[tid];
        #pragma unroll
        for (int o = 4; o; o >>= 1) v += __shfl_xor_sync(0xFFu, v, o);
        if (tid == 0) red[0] = v;
    }
    __syncthreads();

    float vme = red[0] * (1.0f / (float)H_DIM) + EPS_RMS;
    float inv = rsqrtf(vme);
    inv = inv * (1.5f - 0.5f * vme * inv * inv);   // Newton refine

    float4 sv = reinterpret_cast<const float4*>(nsc)[tid];
    float4 tv;
    tv.x = xv.x * inv * sv.x;
    tv.y = xv.y * inv * sv.y;
    tv.z = xv.z * inv * sv.z;
    tv.w = xv.w * inv * sv.w;
    ts[tid * 4 + 0] = tv.x;
    ts[tid * 4 + 1] = tv.y;
    ts[tid * 4 + 2] = tv.z;
    ts[tid * 4 + 3] = tv.w;
    reinterpret_cast<float4*>(d_t + (size_t)b * H_DIM)[tid] = tv;
    __syncthreads();

    const int warp = tid >> 5, lane = tid & 31;
    #pragma unroll
    for (int ee = 0; ee < 4; ee++) {
        const int e = warp * 4 + ee;
        const float* wr = gw + (size_t)e * H_DIM;
        float s = 0.0f;
        #pragma unroll 8
        for (int h = lane; h < H_DIM; h += 32) s = fmaf(ts[h], wr[h], s);
        #pragma unroll
        for (int o = 16; o; o >>= 1) s += __shfl_xor_sync(0xFFFFFFFFu, s, o);
        if (lane == 0) gsm[e] = s + gb[e];
    }
    __syncthreads();

    if (tid == 0) {
        float sv4[TOPK]; int si[TOPK]; unsigned used = 0;
        #pragma unroll
        for (int k = 0; k < TOPK; k++) {
            float best = -1e30f; int bi = 0;
            for (int e = 0; e < N_EXP; e++)
                if (!((used >> e) & 1u) && gsm[e] > best) { best = gsm[e]; bi = e; }
            used |= 1u << bi; sv4[k] = best; si[k] = bi;
        }
        float mx = sv4[0];
        float es[TOPK], sum = 0.0f;
        #pragma unroll
        for (int k = 0; k < TOPK; k++) { es[k] = expf(sv4[k] - mx); sum += es[k]; }
        float rs = 1.0f / sum;
        #pragma unroll
        for (int k = 0; k < TOPK; k++) {
            d_gidx[b * TOPK + k] = si[k];
            d_gw[b * TOPK + k]   = es[k] * rs;
        }
    }
}

// ====================================================================
// K2 (fused): per-expert ranks via warp ballot-scan, offsets, perm fill.
// ====================================================================
__global__ __launch_bounds__(1024)
void perm_kernel()
{
    const int tid = threadIdx.x;
    const int e = tid >> 5, lane = tid & 31;

    int myk[16];
    int myrank[16];
    int cnt = 0;
    #pragma unroll
    for (int c = 0; c < 16; c++) {
        const int t = c * 32 + lane;
        int km = -1;
        #pragma unroll
        for (int k = 0; k < TOPK; k++)
            if (d_gidx[t * TOPK + k] == e) km = k;
        const unsigned m = __ballot_sync(0xFFFFFFFFu, km >= 0);
        myrank[c] = cnt + __popc(m & ((1u << lane) - 1u));
        myk[c] = km;
        cnt += __popc(m);
    }

    __shared__ int scnt[N_EXP], soff[N_EXP];
    if (lane == 0) scnt[e] = cnt;
    __syncthreads();
    if (tid < 32) {
        const int v = scnt[tid];
        int x = v;
        #pragma unroll
        for (int o = 1; o < 32; o <<= 1) {
            const int y = __shfl_up_sync(0xFFFFFFFFu, x, o);
            if (tid >= o) x += y;
        }
        soff[tid]   = x - v;
        d_cnt[tid]  = v;
        d_offs[tid] = x - v;
    }
    __syncthreads();

    const int base = soff[e];
    #pragma unroll
    for (int c = 0; c < 16; c++) {
        if (myk[c] >= 0) {
            const int t = c * 32 + lane;
            const int slot = base + myrank[c];
            d_ptok[slot] = t;
            d_pw[slot]   = d_gw[t * TOPK + myk[c]];
            d_pslot[t * TOPK + myk[c]] = slot;
        }
    }
}

// ====================================================================
// Grouped tf32 tensor-core GEMM.
//   BM=64, BN=64, BK=16, 128 threads (4 warps); warp w owns cols [w*16, w*16+16).
//   3-stage cp.async ring; ldmatrix.x4 operand fetch; raw f32 bits into tf32 MMA.
//   APAD=20: conflict-free ldmatrix phases, 16B-aligned addresses.
// ====================================================================
#define GBM 64
#define GBN 64
#define GBK 16
#define APAD 20
#define STAGES 3

template<bool MLP1>
__global__ __launch_bounds__(128, 6)
void moe_gemm_kernel(const float* __restrict__ W, const float* __restrict__ bias)
{
    const int e   = blockIdx.y;
    const int n_e = d_cnt[e];
    const int m0  = blockIdx.x * GBM;
    if (m0 >= n_e) return;                 // uniform early-exit
    const int NB   = MLP1 ? TWO_I : H_DIM;
    const int n0   = blockIdx.z * GBN;
    const int base = d_offs[e];
    const int tid  = threadIdx.x;
    const int warp = tid >> 5, lane = tid & 31;
    const int g    = lane >> 2, tg = lane & 3;

    __shared__ __align__(16) float As[STAGES][GBM][APAD];
    __shared__ __align__(16) float Bs[STAGES][GBN][APAD];

    // ---- global source pointers (16B chunks: row = tid>>2 (+32i), word = tid&3)
    const float* asrc[2]; int asz[2];
    #pragma unroll
    for (int i = 0; i < 2; i++) {
        const int m   = (tid >> 2) + 32 * i;
        const int row = m0 + m;
        const bool v  = row < n_e;
        const float* p;
        if (MLP1) p = v ? d_t + (size_t)d_ptok[base + row] * H_DIM : d_t;
        else      p = v ? d_a + (size_t)(base + row) * I_DIM       : d_a;
        asrc[i] = p + (tid & 3) * 4;
        asz[i]  = v ? 16 : 0;              // zero-fill padded rows
    }
    // B: 64 rows x 16 k per stage = 256 chunks; thread covers rows tid>>2, +32
    const float* bsrc = W + ((size_t)e * NB + n0 + (tid >> 2)) * 1024 + (tid & 3) * 4;

    // ---- ldmatrix lane addressing
    const int sub = lane >> 3, r8 = lane & 7;
    const int a_r = (sub & 1) * 8 + r8;      // A: row-in-tile
    const int a_c = (sub >> 1) * 4;          // A: word offset 0/4
    const int b_r = (sub >> 1) * 8 + r8;     // B: row-in-16
    const int b_c = (sub & 1) * 4;           // B: word offset 0/4
    const uint32_t sA = (uint32_t)__cvta_generic_to_shared(&As[0][0][0]);
    const uint32_t sB = (uint32_t)__cvta_generic_to_shared(&Bs[0][0][0]);

    float acc[4][2][4];
    #pragma unroll
    for (int a = 0; a < 4; a++)
        #pragma unroll
        for (int b = 0; b < 2; b++)
            #pragma unroll
            for (int c = 0; c < 4; c++) acc[a][b][c] = 0.0f;

    // ---- prologue: stages 0, 1
    #pragma unroll
    for (int s = 0; s < 2; s++) {
        #pragma unroll
        for (int i = 0; i < 2; i++)
            cp_async16(&As[s][(tid >> 2) + 32 * i][(tid & 3) * 4],
                       asrc[i] + s * GBK, asz[i]);
        #pragma unroll
        for (int i = 0; i < 2; i++)
            cp_async16(&Bs[s][(tid >> 2) + 32 * i][(tid & 3) * 4],
                       bsrc + (size_t)32 * i * 1024 + s * GBK, 16);
        cp_commit();
    }

    const int NIT = 1024 / GBK;   // 64
    for (int it = 0; it < NIT; ++it) {
        if (it + 2 < NIT) {
            const int k0 = (it + 2) * GBK;
            const int sb = (it + 2) % STAGES;
            #pragma unroll
            for (int i = 0; i < 2; i++)
                cp_async16(&As[sb][(tid >> 2) + 32 * i][(tid & 3) * 4],
                           asrc[i] + k0, asz[i]);
            #pragma unroll
            for (int i = 0; i < 2; i++)
                cp_async16(&Bs[sb][(tid >> 2) + 32 * i][(tid & 3) * 4],
                           bsrc + (size_t)32 * i * 1024 + k0, 16);
        }
        cp_commit();
        asm volatile("cp.async.wait_group 2;\n" ::: "memory");
        __syncthreads();

        const int buf = it % STAGES;
        const uint32_t aBase = sA + (uint32_t)(buf * GBM * APAD) * 4u;
        const uint32_t bBase = sB + (uint32_t)((buf * GBN + warp * 16) * APAD) * 4u;

        #pragma unroll
        for (int ks = 0; ks < 2; ks++) {
            const int kb = ks * 8;
            uint32_t af[4][4], bf[2][2];
            #pragma unroll
            for (int mt = 0; mt < 4; mt++)
                ldm_x4(af[mt][0], af[mt][1], af[mt][2], af[mt][3],
                       aBase + (uint32_t)(((mt * 16 + a_r) * APAD) + kb + a_c) * 4u);
            ldm_x4(bf[0][0], bf[0][1], bf[1][0], bf[1][1],
                   bBase + (uint32_t)((b_r * APAD) + kb + b_c) * 4u);
            #pragma unroll
            for (int mt = 0; mt < 4; mt++)
                #pragma unroll
                for (int nt = 0; nt < 2; nt++)
                    mma_tf32(acc[mt][nt], af[mt], bf[nt]);
        }
        __syncthreads();
    }

    // ---- epilogue
    if (MLP1) {
        #pragma unroll
        for (int mt = 0; mt < 4; mt++) {
            const int r0 = m0 + mt * 16 + g;
            const int r1 = r0 + 8;
            #pragma unroll
            for (int nt = 0; nt < 2; nt++) {
                const int c = n0 + warp * 16 + nt * 8 + tg * 2;   // even column
                const float bg = bias[(size_t)e * TWO_I + c];
                const float bl = bias[(size_t)e * TWO_I + c + 1];
                if (r0 < n_e) {
                    float hg = fminf(acc[mt][nt][0] + bg, LIMIT_SG);
                    float hl = fminf(fmaxf(acc[mt][nt][1] + bl, -LIMIT_SG), LIMIT_SG);
                    const float sig = 1.0f / (1.0f + expf(-ALPHA_SG * hg));
                    d_a[(size_t)(base + r0) * I_DIM + (c >> 1)] = hg * sig * (hl + 1.0f);
                }
                if (r1 < n_e) {
                    float hg = fminf(acc[mt][nt][2] + bg, LIMIT_SG);
                    float hl = fminf(fmaxf(acc[mt][nt][3] + bl, -LIMIT_SG), LIMIT_SG);
                    const float sig = 1.0f / (1.0f + expf(-ALPHA_SG * hg));
                    d_a[(size_t)(base + r1) * I_DIM + (c >> 1)] = hg * sig * (hl + 1.0f);
                }
            }
        }
    } else {
        #pragma unroll
        for (int mt = 0; mt < 4; mt++) {
            const int r0 = m0 + mt * 16 + g;
            const int r1 = r0 + 8;
            const float pw0 = (r0 < n_e) ? d_pw[base + r0] : 0.0f;
            const float pw1 = (r1 < n_e) ? d_pw[base + r1] : 0.0f;
            #pragma unroll
            for (int nt = 0; nt < 2; nt++) {
                const int c = n0 + warp * 16 + nt * 8 + tg * 2;
                const float b0 = bias[(size_t)e * H_DIM + c];
                const float b1 = bias[(size_t)e * H_DIM + c + 1];
                if (r0 < n_e) {
                    float* orow = d_o + (size_t)(base + r0) * H_DIM;
                    orow[c]     = (acc[mt][nt][0] + b0) * pw0;
                    orow[c + 1] = (acc[mt][nt][1] + b1) * pw0;
                }
                if (r1 < n_e) {
                    float* orow = d_o + (size_t)(base + r1) * H_DIM;
                    orow[c]     = (acc[mt][nt][2] + b0) * pw1;
                    orow[c + 1] = (acc[mt][nt][3] + b1) * pw1;
                }
            }
        }
    }
}

// ====================================================================
// K5: combine: out[b,h] = x[b,h] + sum_k d_o[slot(b,k), h]
// ====================================================================
__global__ __launch_bounds__(256)
void combine_kernel(const float* __restrict__ x, float* __restrict__ out)
{
    const int b   = blockIdx.x;
    const int tid = threadIdx.x;
    float4 acc = reinterpret_cast<const float4*>(x)[b * 256 + tid];
    #pragma unroll
    for (int k = 0; k < TOPK; k++) {
        const int slot = d_pslot[b * TOPK + k];
        float4 ov = reinterpret_cast<const float4*>(d_o + (size_t)slot * H_DIM)[tid];
        acc.x += ov.x; acc.y += ov.y; acc.z += ov.z; acc.w += ov.w;
    }
    reinterpret_cast<float4*>(out)[b * 256 + tid] = acc;
}

// ====================================================================
extern "C" void kernel_launch(void* const* d_in, const int* in_sizes, int n_in,
                              void* d_out, int out_size)
{
    (void)in_sizes; (void)n_in; (void)out_size;
    const float* x   = (const float*)d_in[0];
    const float* nsc = (const float*)d_in[1];
    const float* gw  = (const float*)d_in[2];
    const float* gb  = (const float*)d_in[3];
    const float* w1  = (const float*)d_in[4];
    const float* b1  = (const float*)d_in[5];
    const float* w2  = (const float*)d_in[6];
    const float* b2  = (const float*)d_in[7];
    float* out = (float*)d_out;

    route_kernel<<<B_TOK, 256>>>(x, nsc, gw, gb);
    perm_kernel<<<1, 1024>>>();

    // M-tiles fastest in grid.x -> same-weight-tile blocks schedule-adjacent (L2 reuse)
    dim3 g1(B_TOK / GBM, N_EXP, TWO_I / GBN);   // (8, 32, 32)
    moe_gemm_kernel<true><<<g1, 128>>>(w1, b1);
    dim3 g2(B_TOK / GBM, N_EXP, H_DIM / GBN);   // (8, 32, 16)
    moe_gemm_kernel<false><<<g2, 128>>>(w2, b2);

    combine_kernel<<<B_TOK, 256>>>(x, out);
}

// round 17
// speedup vs baseline: 1.0678x; 1.0678x over previous
#include <cuda_runtime.h>
#include <cstdint>

// ---------------- problem constants ----------------
#define B_TOK  512
#define H_DIM  1024
#define I_DIM  1024
#define TWO_I  2048
#define N_EXP  32
#define TOPK   4
#define NPAIR  (B_TOK * TOPK)   // 2048

#define EPS_RMS   1e-5f
#define ALPHA_SG  1.702f
#define LIMIT_SG  7.0f

// ---------------- scratch (device globals; no allocations allowed) ----------
__device__ float d_t[B_TOK * H_DIM];        // normalized activations (2 MB)
__device__ float d_a[NPAIR * I_DIM];        // swiglu outputs per pair (8 MB)
__device__ float d_o[NPAIR * H_DIM];        // scaled expert outputs (8 MB)
__device__ int   d_gidx[B_TOK * TOPK];
__device__ float d_gw[B_TOK * TOPK];
__device__ int   d_cnt[N_EXP];
__device__ int   d_offs[N_EXP];
__device__ int   d_ptok[NPAIR];
__device__ float d_pw[NPAIR];
__device__ int   d_pslot[B_TOK * TOPK];

// ---------------- PTX helpers ----------------
__device__ __forceinline__ void mma_tf32(float* c, const uint32_t* a, const uint32_t* b) {
    asm volatile(
        "mma.sync.aligned.m16n8k8.row.col.f32.tf32.tf32.f32 "
        "{%0,%1,%2,%3}, {%4,%5,%6,%7}, {%8,%9}, {%0,%1,%2,%3};\n"
        : "+f"(c[0]), "+f"(c[1]), "+f"(c[2]), "+f"(c[3])
        : "r"(a[0]), "r"(a[1]), "r"(a[2]), "r"(a[3]), "r"(b[0]), "r"(b[1]));
}

__device__ __forceinline__ void ldm_x4(uint32_t& r0, uint32_t& r1, uint32_t& r2,
                                       uint32_t& r3, uint32_t addr) {
    asm volatile("ldmatrix.sync.aligned.m8n8.x4.shared.b16 {%0,%1,%2,%3}, [%4];"
                 : "=r"(r0), "=r"(r1), "=r"(r2), "=r"(r3) : "r"(addr));
}

__device__ __forceinline__ void cp_async16(float* dst, const float* src, int bytes = 16) {
    uint32_t s = (uint32_t)__cvta_generic_to_shared(dst);
    asm volatile("cp.async.cg.shared.global [%0], [%1], 16, %2;\n"
                 :: "r"(s), "l"(src), "r"(bytes) : "memory");
}
__device__ __forceinline__ void cp_commit() {
    asm volatile("cp.async.commit_group;\n" ::: "memory");
}

// ====================================================================
// K1: RMSNorm + gate logits + top-4 + softmax.  One block per token.
// ====================================================================
__global__ __launch_bounds__(256)
void route_kernel(const float* __restrict__ x,
                  const float* __restrict__ nsc,
                  const float* __restrict__ gw,
                  const float* __restrict__ gb)
{
    const int b   = blockIdx.x;
    const int tid = threadIdx.x;     // 256

    __shared__ float ts[H_DIM];
    __shared__ float red[8];
    __shared__ float gsm[N_EXP];

    float4 xv = reinterpret_cast<const float4*>(x)[b * 256 + tid];
    float ss = xv.x * xv.x + xv.y * xv.y + xv.z * xv.z + xv.w * xv.w;
    #pragma unroll
    for (int o = 16; o; o >>= 1) ss += __shfl_xor_sync(0xFFFFFFFFu, ss, o);
    if ((tid & 31) == 0) red[tid >> 5] = ss;
    __syncthreads();
    if (tid < 8) {
        float v = red[tid];
        #pragma unroll
        for (int o = 4; o; o >>= 1) v += __shfl_xor_sync(0xFFu, v, o);
        if (tid == 0) red[0] = v;
    }
    __syncthreads();

    float vme = red[0] * (1.0f / (float)H_DIM) + EPS_RMS;
    float inv = rsqrtf(vme);
    inv = inv * (1.5f - 0.5f * vme * inv * inv);   // Newton refine

    float4 sv = reinterpret_cast<const float4*>(nsc)[tid];
    float4 tv;
    tv.x = xv.x * inv * sv.x;
    tv.y = xv.y * inv * sv.y;
    tv.z = xv.z * inv * sv.z;
    tv.w = xv.w * inv * sv.w;
    ts[tid * 4 + 0] = tv.x;
    ts[tid * 4 + 1] = tv.y;
    ts[tid * 4 + 2] = tv.z;
    ts[tid * 4 + 3] = tv.w;
    reinterpret_cast<float4*>(d_t + (size_t)b * H_DIM)[tid] = tv;
    __syncthreads();

    const int warp = tid >> 5, lane = tid & 31;
    #pragma unroll
    for (int ee = 0; ee < 4; ee++) {
        const int e = warp * 4 + ee;
        const float* wr = gw + (size_t)e * H_DIM;
        float s = 0.0f;
        #pragma unroll 8
        for (int h = lane; h < H_DIM; h += 32) s = fmaf(ts[h], wr[h], s);
        #pragma unroll
        for (int o = 16; o; o >>= 1) s += __shfl_xor_sync(0xFFFFFFFFu, s, o);
        if (lane == 0) gsm[e] = s + gb[e];
    }
    __syncthreads();

    if (tid == 0) {
        float sv4[TOPK]; int si[TOPK]; unsigned used = 0;
        #pragma unroll
        for (int k = 0; k < TOPK; k++) {
            float best = -1e30f; int bi = 0;
            for (int e = 0; e < N_EXP; e++)
                if (!((used >> e) & 1u) && gsm[e] > best) { best = gsm[e]; bi = e; }
            used |= 1u << bi; sv4[k] = best; si[k] = bi;
        }
        float mx = sv4[0];
        float es[TOPK], sum = 0.0f;
        #pragma unroll
        for (int k = 0; k < TOPK; k++) { es[k] = expf(sv4[k] - mx); sum += es[k]; }
        float rs = 1.0f / sum;
        #pragma unroll
        for (int k = 0; k < TOPK; k++) {
            d_gidx[b * TOPK + k] = si[k];
            d_gw[b * TOPK + k]   = es[k] * rs;
        }
    }
}

// ====================================================================
// K2 (fused): per-expert ranks via warp ballot-scan, offsets, perm fill.
// ====================================================================
__global__ __launch_bounds__(1024)
void perm_kernel()
{
    const int tid = threadIdx.x;
    const int e = tid >> 5, lane = tid & 31;

    int myk[16];
    int myrank[16];
    int cnt = 0;
    #pragma unroll
    for (int c = 0; c < 16; c++) {
        const int t = c * 32 + lane;
        int km = -1;
        #pragma unroll
        for (int k = 0; k < TOPK; k++)
            if (d_gidx[t * TOPK + k] == e) km = k;
        const unsigned m = __ballot_sync(0xFFFFFFFFu, km >= 0);
        myrank[c] = cnt + __popc(m & ((1u << lane) - 1u));
        myk[c] = km;
        cnt += __popc(m);
    }

    __shared__ int scnt[N_EXP], soff[N_EXP];
    if (lane == 0) scnt[e] = cnt;
    __syncthreads();
    if (tid < 32) {
        const int v = scnt[tid];
        int x = v;
        #pragma unroll
        for (int o = 1; o < 32; o <<= 1) {
            const int y = __shfl_up_sync(0xFFFFFFFFu, x, o);
            if (tid >= o) x += y;
        }
        soff[tid]   = x - v;
        d_cnt[tid]  = v;
        d_offs[tid] = x - v;
    }
    __syncthreads();

    const int base = soff[e];
    #pragma unroll
    for (int c = 0; c < 16; c++) {
        if (myk[c] >= 0) {
            const int t = c * 32 + lane;
            const int slot = base + myrank[c];
            d_ptok[slot] = t;
            d_pw[slot]   = d_gw[t * TOPK + myk[c]];
            d_pslot[t * TOPK + myk[c]] = slot;
        }
    }
}

// ====================================================================
// Grouped tf32 tensor-core GEMM (multistage).
//   BM=64, BN=64, BK=16, 128 threads (4 warps); warp w owns cols [w*16,w*16+16).
//   5-stage cp.async ring (prefetch distance 4 k-tiles >= DRAM latency),
//   ONE __syncthreads per iter (write slots it+1..it+4 never alias read slot it).
//   ldmatrix.x4 operand fetch; raw f32 bits into tf32 MMA (RZ rounding).
// ====================================================================
#define GBM 64
#define GBN 64
#define GBK 16
#define APAD 20
#define STAGES 5

template<bool MLP1>
__global__ __launch_bounds__(128, 4)
void moe_gemm_kernel(const float* __restrict__ W, const float* __restrict__ bias)
{
    const int e   = blockIdx.y;
    const int n_e = d_cnt[e];
    const int m0  = blockIdx.x * GBM;
    if (m0 >= n_e) return;                 // uniform early-exit
    const int NB   = MLP1 ? TWO_I : H_DIM;
    const int n0   = blockIdx.z * GBN;
    const int base = d_offs[e];
    const int tid  = threadIdx.x;
    const int warp = tid >> 5, lane = tid & 31;
    const int g    = lane >> 2, tg = lane & 3;

    __shared__ __align__(16) float As[STAGES][GBM][APAD];
    __shared__ __align__(16) float Bs[STAGES][GBN][APAD];

    // ---- global source pointers (16B chunks: row = tid>>2 (+32i), word = tid&3)
    const float* asrc[2]; int asz[2];
    #pragma unroll
    for (int i = 0; i < 2; i++) {
        const int m   = (tid >> 2) + 32 * i;
        const int row = m0 + m;
        const bool v  = row < n_e;
        const float* p;
        if (MLP1) p = v ? d_t + (size_t)d_ptok[base + row] * H_DIM : d_t;
        else      p = v ? d_a + (size_t)(base + row) * I_DIM       : d_a;
        asrc[i] = p + (tid & 3) * 4;
        asz[i]  = v ? 16 : 0;              // zero-fill padded rows
    }
    const float* bsrc = W + ((size_t)e * NB + n0 + (tid >> 2)) * 1024 + (tid & 3) * 4;

    // ---- ldmatrix lane addressing
    const int sub = lane >> 3, r8 = lane & 7;
    const int a_r = (sub & 1) * 8 + r8;      // A: row-in-tile
    const int a_c = (sub >> 1) * 4;          // A: word offset 0/4
    const int b_r = (sub >> 1) * 8 + r8;     // B: row-in-16
    const int b_c = (sub & 1) * 4;           // B: word offset 0/4
    const uint32_t sA = (uint32_t)__cvta_generic_to_shared(&As[0][0][0]);
    const uint32_t sB = (uint32_t)__cvta_generic_to_shared(&Bs[0][0][0]);

    float acc[4][2][4];
    #pragma unroll
    for (int a = 0; a < 4; a++)
        #pragma unroll
        for (int b = 0; b < 2; b++)
            #pragma unroll
            for (int c = 0; c < 4; c++) acc[a][b][c] = 0.0f;

    // ---- prologue: stages 0..3 (4 groups in flight)
    #pragma unroll
    for (int s = 0; s < STAGES - 1; s++) {
        #pragma unroll
        for (int i = 0; i < 2; i++)
            cp_async16(&As[s][(tid >> 2) + 32 * i][(tid & 3) * 4],
                       asrc[i] + s * GBK, asz[i]);
        #pragma unroll
        for (int i = 0; i < 2; i++)
            cp_async16(&Bs[s][(tid >> 2) + 32 * i][(tid & 3) * 4],
                       bsrc + (size_t)32 * i * 1024 + s * GBK, 16);
        cp_commit();
    }

    const int NIT = 1024 / GBK;   // 64
    for (int it = 0; it < NIT; ++it) {
        // stage it%STAGES is complete once <= STAGES-2 groups remain pending
        asm volatile("cp.async.wait_group %0;\n" :: "n"(STAGES - 2) : "memory");
        __syncthreads();

        // prefetch k-tile it+4 into slot (it+4)%5 (never aliases read slot it%5)
        if (it + STAGES - 1 < NIT) {
            const int k0 = (it + STAGES - 1) * GBK;
            const int sb = (it + STAGES - 1) % STAGES;
            #pragma unroll
            for (int i = 0; i < 2; i++)
                cp_async16(&As[sb][(tid >> 2) + 32 * i][(tid & 3) * 4],
                           asrc[i] + k0, asz[i]);
            #pragma unroll
            for (int i = 0; i < 2; i++)
                cp_async16(&Bs[sb][(tid >> 2) + 32 * i][(tid & 3) * 4],
                           bsrc + (size_t)32 * i * 1024 + k0, 16);
        }
        cp_commit();   // always commit (empty groups keep wait counts consistent)

        const int buf = it % STAGES;
        const uint32_t aBase = sA + (uint32_t)(buf * GBM * APAD) * 4u;
        const uint32_t bBase = sB + (uint32_t)((buf * GBN + warp * 16) * APAD) * 4u;

        #pragma unroll
        for (int ks = 0; ks < 2; ks++) {
            const int kb = ks * 8;
            uint32_t af[4][4], bf[2][2];
            #pragma unroll
            for (int mt = 0; mt < 4; mt++)
                ldm_x4(af[mt][0], af[mt][1], af[mt][2], af[mt][3],
                       aBase + (uint32_t)(((mt * 16 + a_r) * APAD) + kb + a_c) * 4u);
            ldm_x4(bf[0][0], bf[0][1], bf[1][0], bf[1][1],
                   bBase + (uint32_t)((b_r * APAD) + kb + b_c) * 4u);
            #pragma unroll
            for (int mt = 0; mt < 4; mt++)
                #pragma unroll
                for (int nt = 0; nt < 2; nt++)
                    mma_tf32(acc[mt][nt], af[mt], bf[nt]);
        }
        // no trailing barrier: next iter's writes can't touch slot being read
    }

    // ---- epilogue
    if (MLP1) {
        #pragma unroll
        for (int mt = 0; mt < 4; mt++) {
            const int r0 = m0 + mt * 16 + g;
            const int r1 = r0 + 8;
            #pragma unroll
            for (int nt = 0; nt < 2; nt++) {
                const int c = n0 + warp * 16 + nt * 8 + tg * 2;   // even column
                const float bg = bias[(size_t)e * TWO_I + c];
                const float bl = bias[(size_t)e * TWO_I + c + 1];
                if (r0 < n_e) {
                    float hg = fminf(acc[mt][nt][0] + bg, LIMIT_SG);
                    float hl = fminf(fmaxf(acc[mt][nt][1] + bl, -LIMIT_SG), LIMIT_SG);
                    const float sig = 1.0f / (1.0f + expf(-ALPHA_SG * hg));
                    d_a[(size_t)(base + r0) * I_DIM + (c >> 1)] = hg * sig * (hl + 1.0f);
                }
                if (r1 < n_e) {
                    float hg = fminf(acc[mt][nt][2] + bg, LIMIT_SG);
                    float hl = fminf(fmaxf(acc[mt][nt][3] + bl, -LIMIT_SG), LIMIT_SG);
                    const float sig = 1.0f / (1.0f + expf(-ALPHA_SG * hg));
                    d_a[(size_t)(base + r1) * I_DIM + (c >> 1)] = hg * sig * (hl + 1.0f);
                }
            }
        }
    } else {
        #pragma unroll
        for (int mt = 0; mt < 4; mt++) {
            const int r0 = m0 + mt * 16 + g;
            const int r1 = r0 + 8;
            const float pw0 = (r0 < n_e) ? d_pw[base + r0] : 0.0f;
            const float pw1 = (r1 < n_e) ? d_pw[base + r1] : 0.0f;
            #pragma unroll
            for (int nt = 0; nt < 2; nt++) {
                const int c = n0 + warp * 16 + nt * 8 + tg * 2;
                const float b0 = bias[(size_t)e * H_DIM + c];
                const float b1 = bias[(size_t)e * H_DIM + c + 1];
                if (r0 < n_e) {
                    float* orow = d_o + (size_t)(base + r0) * H_DIM;
                    orow[c]     = (acc[mt][nt][0] + b0) * pw0;
                    orow[c + 1] = (acc[mt][nt][1] + b1) * pw0;
                }
                if (r1 < n_e) {
                    float* orow = d_o + (size_t)(base + r1) * H_DIM;
                    orow[c]     = (acc[mt][nt][2] + b0) * pw1;
                    orow[c + 1] = (acc[mt][nt][3] + b1) * pw1;
                }
            }
        }
    }
}

// ====================================================================
// K5: combine: out[b,h] = x[b,h] + sum_k d_o[slot(b,k), h]
// ====================================================================
__global__ __launch_bounds__(256)
void combine_kernel(const float* __restrict__ x, float* __restrict__ out)
{
    const int b   = blockIdx.x;
    const int tid = threadIdx.x;
    float4 acc = reinterpret_cast<const float4*>(x)[b * 256 + tid];
    #pragma unroll
    for (int k = 0; k < TOPK; k++) {
        const int slot = d_pslot[b * TOPK + k];
        float4 ov = reinterpret_cast<const float4*>(d_o + (size_t)slot * H_DIM)[tid];
        acc.x += ov.x; acc.y += ov.y; acc.z += ov.z; acc.w += ov.w;
    }
    reinterpret_cast<float4*>(out)[b * 256 + tid] = acc;
}

// ====================================================================
extern "C" void kernel_launch(void* const* d_in, const int* in_sizes, int n_in,
                              void* d_out, int out_size)
{
    (void)in_sizes; (void)n_in; (void)out_size;
    const float* x   = (const float*)d_in[0];
    const float* nsc = (const float*)d_in[1];
    const float* gw  = (const float*)d_in[2];
    const float* gb  = (const float*)d_in[3];
    const float* w1  = (const float*)d_in[4];
    const float* b1  = (const float*)d_in[5];
    const float* w2  = (const float*)d_in[6];
    const float* b2  = (const float*)d_in[7];
    float* out = (float*)d_out;

    route_kernel<<<B_TOK, 256>>>(x, nsc, gw, gb);
    perm_kernel<<<1, 1024>>>();

    // M-tiles fastest in grid.x -> same-weight-tile blocks schedule-adjacent (L2 reuse)
    dim3 g1(B_TOK / GBM, N_EXP, TWO_I / GBN);   // (8, 32, 32)
    moe_gemm_kernel<true><<<g1, 128>>>(w1, b1);
    dim3 g2(B_TOK / GBM, N_EXP, H_DIM / GBN);   // (8, 32, 16)
    moe_gemm_kernel<false><<<g2, 128>>>(w2, b2);

    combine_kernel<<<B_TOK, 256>>>(x, out);
}